// round 3
// baseline (speedup 1.0000x reference)
#include <cuda_runtime.h>
#include <cuda_bf16.h>
#include <cstdint>

// Greedy CTC decode:
//   emission: [T, V=128] fp32
//   out (fp32, 3*T): [ idx(0:T) | keep(T:2T) | path_score(2T:3T) ]
//
// Kernel 1: persistent grid-stride. Each warp owns a sequence of 8-row tiles;
//           double-buffered prefetch keeps 8 LDG.128s in flight while the
//           previous tile reduces (float-domain local argmax, fmono + REDUX +
//           ballot for first-occurrence warp argmax).
// Kernel 2: vectorized run-length dedup + score masking, 8 elems/thread.

#define V 128
#define BLANK 0
#define WARPS_PER_BLOCK 8
#define ROWS_PER_WARP 8
#define ARGMAX_GRID 1024
#define FULL_MASK 0xFFFFFFFFu

// Order-preserving fp32 bits -> u32 map and inverse.
__device__ __forceinline__ unsigned fmono(float f) {
    unsigned b = __float_as_uint(f);
    return b ^ ((unsigned)((int)b >> 31) | 0x80000000u);
}
__device__ __forceinline__ float funmono(unsigned u) {
    unsigned b = u ^ ((unsigned)((int)(~u) >> 31) | 0x80000000u);
    return __uint_as_float(b);
}

__device__ __forceinline__ void load_tile(const float* __restrict__ em,
                                          int base, int lane, float4* v)
{
    #pragma unroll
    for (int k = 0; k < ROWS_PER_WARP; k++) {
        v[k] = __ldcs(reinterpret_cast<const float4*>(em + (size_t)(base + k) * V) + lane);
    }
}

__device__ __forceinline__ void process_tile(const float4* v, int base, int lane,
                                             float* __restrict__ out_idx,
                                             float* __restrict__ out_max)
{
    float res_idx[ROWS_PER_WARP];
    float res_max[ROWS_PER_WARP];

    #pragma unroll
    for (int k = 0; k < ROWS_PER_WARP; k++) {
        // Local argmax over this lane's 4 columns, float domain.
        // Strict > keeps the earliest column.
        float best = v[k].x; int bi = lane * 4;
        if (v[k].y > best) { best = v[k].y; bi = lane * 4 + 1; }
        if (v[k].z > best) { best = v[k].z; bi = lane * 4 + 2; }
        if (v[k].w > best) { best = v[k].w; bi = lane * 4 + 3; }

        unsigned key  = fmono(best);
        unsigned wmax = __reduce_max_sync(FULL_MASK, key);
        unsigned ball = __ballot_sync(FULL_MASK, key == wmax);
        int src  = __ffs(ball) - 1;              // lowest lane = lowest column
        int widx = __shfl_sync(FULL_MASK, bi, src);

        res_idx[k] = (float)widx;
        res_max[k] = funmono(wmax);
    }

    if (lane == 0) {
        // base is a multiple of 8 -> 16B-aligned float4 stores
        reinterpret_cast<float4*>(out_idx + base)[0] =
            make_float4(res_idx[0], res_idx[1], res_idx[2], res_idx[3]);
        reinterpret_cast<float4*>(out_idx + base)[1] =
            make_float4(res_idx[4], res_idx[5], res_idx[6], res_idx[7]);
        reinterpret_cast<float4*>(out_max + base)[0] =
            make_float4(res_max[0], res_max[1], res_max[2], res_max[3]);
        reinterpret_cast<float4*>(out_max + base)[1] =
            make_float4(res_max[4], res_max[5], res_max[6], res_max[7]);
    }
}

__global__ void __launch_bounds__(WARPS_PER_BLOCK * 32)
ctc_argmax_kernel(const float* __restrict__ em,
                  float* __restrict__ out_idx,
                  float* __restrict__ out_max,
                  int rows)
{
    const int lane   = threadIdx.x & 31;
    const int ntiles = rows / ROWS_PER_WARP;                     // 131072
    const int stride = gridDim.x * WARPS_PER_BLOCK;              // warp-tiles per step
    int tile = blockIdx.x * WARPS_PER_BLOCK + (threadIdx.x >> 5);
    if (tile >= ntiles) return;

    float4 buf[2][ROWS_PER_WARP];
    load_tile(em, tile * ROWS_PER_WARP, lane, buf[0]);
    int p = 0;

    #pragma unroll 2
    for (; tile < ntiles; tile += stride) {
        int nxt = tile + stride;
        if (nxt < ntiles)
            load_tile(em, nxt * ROWS_PER_WARP, lane, buf[p ^ 1]);  // prefetch
        process_tile(buf[p], tile * ROWS_PER_WARP, lane, out_idx, out_max);
        p ^= 1;
    }
}

__global__ void __launch_bounds__(256)
ctc_dedup_kernel(const float* __restrict__ idx_f,   // out[0:T]
                 float* __restrict__ keep_f,        // out[T:2T]
                 float* __restrict__ score_f,       // out[2T:3T]: max in, score out
                 int rows)
{
    int nvec = rows / 4;
    int stride = gridDim.x * blockDim.x;
    for (int i = blockIdx.x * blockDim.x + threadIdx.x; i < nvec; i += stride) {
        int t = i * 4;
        float4 c = reinterpret_cast<const float4*>(idx_f)[i];
        float4 s = reinterpret_cast<const float4*>(score_f)[i];
        float prev0 = (t > 0) ? idx_f[t - 1] : -1.0f;

        bool k0 = (c.x != prev0) && (c.x != (float)BLANK);
        bool k1 = (c.y != c.x)   && (c.y != (float)BLANK);
        bool k2 = (c.z != c.y)   && (c.z != (float)BLANK);
        bool k3 = (c.w != c.z)   && (c.w != (float)BLANK);

        reinterpret_cast<float4*>(keep_f)[i] =
            make_float4(k0 ? 1.0f : 0.0f, k1 ? 1.0f : 0.0f,
                        k2 ? 1.0f : 0.0f, k3 ? 1.0f : 0.0f);
        reinterpret_cast<float4*>(score_f)[i] =
            make_float4(k0 ? s.x : 0.0f, k1 ? s.y : 0.0f,
                        k2 ? s.z : 0.0f, k3 ? s.w : 0.0f);
    }
}

extern "C" void kernel_launch(void* const* d_in, const int* in_sizes, int n_in,
                              void* d_out, int out_size)
{
    const float* em = (const float*)d_in[0];
    float* out = (float*)d_out;

    const int rows = in_sizes[0] / V;            // T = 1048576
    float* out_idx   = out;                      // [0:T)
    float* out_keep  = out + rows;               // [T:2T)
    float* out_score = out + 2 * (size_t)rows;   // [2T:3T)

    {
        dim3 block(WARPS_PER_BLOCK * 32);
        dim3 grid(ARGMAX_GRID);
        ctc_argmax_kernel<<<grid, block>>>(em, out_idx, out_score, rows);
    }
    {
        dim3 block(256);
        dim3 grid(512);
        ctc_dedup_kernel<<<grid, block>>>(out_idx, out_keep, out_score, rows);
    }
}